// round 17
// baseline (speedup 1.0000x reference)
#include <cuda_runtime.h>
#include <cuda_bf16.h>
#include <cstdint>

// RNNModel: T=512, B=256, I=256, H=512, fp32.
//   K1: xp = x @ w_ih^T + (b_ih+b_hh)   -> 3xbf16 mma.sync k16 GEMM (R16 proven, unchanged)
//   K2: h_t = tanh(xp_t + h @ w_hh^T)   -> bf16x2 mma.sync persistent; 3 accumulator chains,
//                                          two-phase cp.async staging, per-warp release
//   K3: out = hs @ w_fc^T + b_fc        -> 3xbf16 GEMM, A pre-split (R16 proven, unchanged)

#define T_ 512
#define B_ 256
#define I_ 256
#define H_ 512

#define NG  16
#define NSL 8
#define BT  16
#define NS  64
#define KS32 260   // K2 smem u32 row stride (frag loads hit 32 banks)

__device__ float    g_xp[(size_t)T_ * B_ * H_];
__device__ uint32_t g_h1f[(size_t)T_ * B_ * (H_ / 2)];   // bf16x2 big,  full history
__device__ uint32_t g_h2f[(size_t)T_ * B_ * (H_ / 2)];   // bf16x2 resid, full history
__device__ int      g_cnt[NG];

// ---------------- helpers ----------------
__device__ __forceinline__ uint32_t smem_u32(const void* p) {
    uint32_t a;
    asm("{ .reg .u64 t; cvta.to.shared.u64 t, %1; cvt.u32.u64 %0, t; }" : "=r"(a) : "l"(p));
    return a;
}
__device__ __forceinline__ void cp_async16(uint32_t saddr, const void* gptr) {
    asm volatile("cp.async.ca.shared.global [%0], [%1], 16;" :: "r"(saddr), "l"(gptr));
}
#define CP_COMMIT() asm volatile("cp.async.commit_group;" ::: "memory")
#define CP_WAIT(n)  asm volatile("cp.async.wait_group %0;" :: "n"(n) : "memory")
#define CP_COMMIT_WAIT() \
    asm volatile("cp.async.commit_group;\n\tcp.async.wait_group 0;" ::: "memory")

__device__ __forceinline__ void mma16n8k16_bf16(float* c, const uint32_t* a, const uint32_t* b) {
    asm volatile("mma.sync.aligned.m16n8k16.row.col.f32.bf16.bf16.f32 "
        "{%0,%1,%2,%3}, {%4,%5,%6,%7}, {%8,%9}, {%0,%1,%2,%3};"
        : "+f"(c[0]), "+f"(c[1]), "+f"(c[2]), "+f"(c[3])
        : "r"(a[0]), "r"(a[1]), "r"(a[2]), "r"(a[3]), "r"(b[0]), "r"(b[1]));
}
__device__ __forceinline__ uint32_t bf2_pack(float f0, float f1) {
    __nv_bfloat162 p = __floats2bfloat162_rn(f0, f1);
    return *reinterpret_cast<uint32_t*>(&p);
}
__device__ __forceinline__ void split_pair(float f0, float f1, uint32_t& big, uint32_t& res) {
    const __nv_bfloat162 b = __floats2bfloat162_rn(f0, f1);
    big = *reinterpret_cast<const uint32_t*>(&b);
    res = bf2_pack(f0 - __low2float(b), f1 - __high2float(b));
}

// ================= 3xbf16 GEMM (R16 verbatim) =================
#define PADB 20
#define ARRU (128 * PADB)
#define STGU (4 * ARRU)
#define GEMM_SMEM_BYTES (2 * STGU * 4)   // 81920

#define BF16_CHUNK_COMPUTE(A1p_, A2p_, B1p_, B2p_)                                   \
    do {                                                                             \
        _Pragma("unroll")                                                            \
        for (int kb = 0; kb < 2; kb++) {                                             \
            const int off = kb * 8 + tig;                                            \
            uint32_t a1[2][4], a2[2][4], b1f[8][2], b2f[8][2];                       \
            _Pragma("unroll")                                                        \
            for (int mt = 0; mt < 2; mt++) {                                         \
                const int r = (wm << 5) + (mt << 4) + gid;                           \
                a1[mt][0] = (A1p_)[r * PADB + off];                                  \
                a1[mt][1] = (A1p_)[(r + 8) * PADB + off];                            \
                a1[mt][2] = (A1p_)[r * PADB + off + 4];                              \
                a1[mt][3] = (A1p_)[(r + 8) * PADB + off + 4];                        \
                a2[mt][0] = (A2p_)[r * PADB + off];                                  \
                a2[mt][1] = (A2p_)[(r + 8) * PADB + off];                            \
                a2[mt][2] = (A2p_)[r * PADB + off + 4];                              \
                a2[mt][3] = (A2p_)[(r + 8) * PADB + off + 4];                        \
            }                                                                        \
            _Pragma("unroll")                                                        \
            for (int nt = 0; nt < 8; nt++) {                                         \
                const int nn = (wn << 6) + (nt << 3) + gid;                          \
                b1f[nt][0] = (B1p_)[nn * PADB + off];                                \
                b1f[nt][1] = (B1p_)[nn * PADB + off + 4];                            \
                b2f[nt][0] = (B2p_)[nn * PADB + off];                                \
                b2f[nt][1] = (B2p_)[nn * PADB + off + 4];                            \
            }                                                                        \
            _Pragma("unroll")                                                        \
            for (int mt = 0; mt < 2; mt++)                                           \
                _Pragma("unroll")                                                    \
                for (int nt = 0; nt < 8; nt++) {                                     \
                    mma16n8k16_bf16(acc[mt][nt], a1[mt], b1f[nt]);                   \
                    mma16n8k16_bf16(acc[mt][nt], a2[mt], b1f[nt]);                   \
                    mma16n8k16_bf16(acc[mt][nt], a1[mt], b2f[nt]);                   \
                }                                                                    \
        }                                                                            \
    } while (0)

#define BF16_EPILOGUE()                                                              \
    do {                                                                             \
        float bias[8][2];                                                            \
        _Pragma("unroll")                                                            \
        for (int nt = 0; nt < 8; nt++) {                                             \
            const int col = n0 + (wn << 6) + (nt << 3) + (tig << 1);                 \
            float v0 = b1[col], v1 = b1[col + 1];                                    \
            if (b2) { v0 += b2[col]; v1 += b2[col + 1]; }                            \
            bias[nt][0] = v0; bias[nt][1] = v1;                                      \
        }                                                                            \
        _Pragma("unroll")                                                            \
        for (int mt = 0; mt < 2; mt++)                                               \
            _Pragma("unroll")                                                        \
            for (int half = 0; half < 2; half++) {                                   \
                const int row = m0 + (wm << 5) + (mt << 4) + gid + (half << 3);      \
                float* crow = C + (size_t)row * N;                                   \
                _Pragma("unroll")                                                    \
                for (int nt = 0; nt < 8; nt++) {                                     \
                    const int col = n0 + (wn << 6) + (nt << 3) + (tig << 1);         \
                    float2 v;                                                        \
                    v.x = acc[mt][nt][half * 2 + 0] + bias[nt][0];                   \
                    v.y = acc[mt][nt][half * 2 + 1] + bias[nt][1];                   \
                    *(float2*)(crow + col) = v;                                      \
                }                                                                    \
            }                                                                        \
    } while (0)

// ---------------- K1: fp32 A,B -> split in loader ----------------
__global__ void __launch_bounds__(256, 2) bf16_gemm_f32_kernel(
    const float* __restrict__ A, const float* __restrict__ Bm,
    const float* __restrict__ b1, const float* __restrict__ b2,
    float* __restrict__ C, int M, int N, int K)
{
    extern __shared__ uint32_t su[];
    const int tid = threadIdx.x;
    const int m0 = blockIdx.y << 7;
    const int n0 = blockIdx.x << 7;
    const int lane = tid & 31, wid = tid >> 5;
    const int gid = lane >> 2, tig = lane & 3;
    const int wm = wid >> 1, wn = wid & 1;

    const int lrow = tid >> 1;
    const int lko  = (tid & 1) << 4;
    const int sa   = lrow * PADB + (lko >> 1);

    const float* Ap = A + (size_t)(m0 + lrow) * K + lko;
    const float* Bp = Bm + (size_t)(n0 + lrow) * K + lko;

    float acc[2][8][4];
#pragma unroll
    for (int mt = 0; mt < 2; mt++)
#pragma unroll
        for (int nt = 0; nt < 8; nt++)
#pragma unroll
            for (int i = 0; i < 4; i++) acc[mt][nt][i] = 0.0f;

    const int NC = K >> 5;

    float4 ar[4], br[4];
#pragma unroll
    for (int i = 0; i < 4; i++) {
        ar[i] = *(const float4*)(Ap + 4 * i);
        br[i] = *(const float4*)(Bp + 4 * i);
    }

    for (int kc = 0; kc < NC; kc++) {
        const int s = kc & 1;
        uint32_t* A1 = su + s * STGU;
        uint32_t* A2 = A1 + ARRU;
        uint32_t* B1 = A2 + ARRU;
        uint32_t* B2 = B1 + ARRU;

        {
            uint4 bg, rs;
            split_pair(ar[0].x, ar[0].y, bg.x, rs.x);
            split_pair(ar[0].z, ar[0].w, bg.y, rs.y);
            split_pair(ar[1].x, ar[1].y, bg.z, rs.z);
            split_pair(ar[1].z, ar[1].w, bg.w, rs.w);
            *(uint4*)(A1 + sa) = bg; *(uint4*)(A2 + sa) = rs;
            split_pair(ar[2].x, ar[2].y, bg.x, rs.x);
            split_pair(ar[2].z, ar[2].w, bg.y, rs.y);
            split_pair(ar[3].x, ar[3].y, bg.z, rs.z);
            split_pair(ar[3].z, ar[3].w, bg.w, rs.w);
            *(uint4*)(A1 + sa + 4) = bg; *(uint4*)(A2 + sa + 4) = rs;

            split_pair(br[0].x, br[0].y, bg.x, rs.x);
            split_pair(br[0].z, br[0].w, bg.y, rs.y);
            split_pair(br[1].x, br[1].y, bg.z, rs.z);
            split_pair(br[1].z, br[1].w, bg.w, rs.w);
            *(uint4*)(B1 + sa) = bg; *(uint4*)(B2 + sa) = rs;
            split_pair(br[2].x, br[2].y, bg.x, rs.x);
            split_pair(br[2].z, br[2].w, bg.y, rs.y);
            split_pair(br[3].x, br[3].y, bg.z, rs.z);
            split_pair(br[3].z, br[3].w, bg.w, rs.w);
            *(uint4*)(B1 + sa + 4) = bg; *(uint4*)(B2 + sa + 4) = rs;
        }
        __syncthreads();

        if (kc + 1 < NC) {
            const int K0 = (kc + 1) << 5;
#pragma unroll
            for (int i = 0; i < 4; i++) {
                ar[i] = *(const float4*)(Ap + K0 + 4 * i);
                br[i] = *(const float4*)(Bp + K0 + 4 * i);
            }
        }

        BF16_CHUNK_COMPUTE(A1, A2, B1, B2);
        __syncthreads();
    }

    BF16_EPILOGUE();
}

// ---------------- K3: A pre-split, B fp32 split in loader ----------------
__global__ void __launch_bounds__(256, 2) bf16_gemm_preA_kernel(
    const uint32_t* __restrict__ A1g, const uint32_t* __restrict__ A2g,
    const float* __restrict__ Bm,
    const float* __restrict__ b1, const float* __restrict__ b2,
    float* __restrict__ C, int M, int N, int K)
{
    extern __shared__ uint32_t su[];
    const int tid = threadIdx.x;
    const int m0 = blockIdx.y << 7;
    const int n0 = blockIdx.x << 7;
    const int lane = tid & 31, wid = tid >> 5;
    const int gid = lane >> 2, tig = lane & 3;
    const int wm = wid >> 1, wn = wid & 1;

    const int lrow = tid >> 1;
    const int lko  = (tid & 1) << 4;
    const int lkp  = lko >> 1;
    const int sa   = lrow * PADB + lkp;
    const int KP   = K >> 1;

    const uint32_t* A1p = A1g + (size_t)(m0 + lrow) * KP + lkp;
    const uint32_t* A2p = A2g + (size_t)(m0 + lrow) * KP + lkp;
    const float*    Bp  = Bm + (size_t)(n0 + lrow) * K + lko;

    float acc[2][8][4];
#pragma unroll
    for (int mt = 0; mt < 2; mt++)
#pragma unroll
        for (int nt = 0; nt < 8; nt++)
#pragma unroll
            for (int i = 0; i < 4; i++) acc[mt][nt][i] = 0.0f;

    const int NC = K >> 5;

    uint4 a1r0 = *(const uint4*)(A1p);
    uint4 a1r1 = *(const uint4*)(A1p + 4);
    uint4 a2r0 = *(const uint4*)(A2p);
    uint4 a2r1 = *(const uint4*)(A2p + 4);
    float4 br[4];
#pragma unroll
    for (int i = 0; i < 4; i++) br[i] = *(const float4*)(Bp + 4 * i);

    for (int kc = 0; kc < NC; kc++) {
        const int s = kc & 1;
        uint32_t* A1 = su + s * STGU;
        uint32_t* A2 = A1 + ARRU;
        uint32_t* B1 = A2 + ARRU;
        uint32_t* B2 = B1 + ARRU;

        {
            *(uint4*)(A1 + sa)     = a1r0;
            *(uint4*)(A1 + sa + 4) = a1r1;
            *(uint4*)(A2 + sa)     = a2r0;
            *(uint4*)(A2 + sa + 4) = a2r1;
            uint4 bg, rs;
            split_pair(br[0].x, br[0].y, bg.x, rs.x);
            split_pair(br[0].z, br[0].w, bg.y, rs.y);
            split_pair(br[1].x, br[1].y, bg.z, rs.z);
            split_pair(br[1].z, br[1].w, bg.w, rs.w);
            *(uint4*)(B1 + sa) = bg; *(uint4*)(B2 + sa) = rs;
            split_pair(br[2].x, br[2].y, bg.x, rs.x);
            split_pair(br[2].z, br[2].w, bg.y, rs.y);
            split_pair(br[3].x, br[3].y, bg.z, rs.z);
            split_pair(br[3].z, br[3].w, bg.w, rs.w);
            *(uint4*)(B1 + sa + 4) = bg; *(uint4*)(B2 + sa + 4) = rs;
        }
        __syncthreads();

        if (kc + 1 < NC) {
            const int P0 = (kc + 1) << 4;
            a1r0 = *(const uint4*)(A1p + P0);
            a1r1 = *(const uint4*)(A1p + P0 + 4);
            a2r0 = *(const uint4*)(A2p + P0);
            a2r1 = *(const uint4*)(A2p + P0 + 4);
            const int K0 = (kc + 1) << 5;
#pragma unroll
            for (int i = 0; i < 4; i++) br[i] = *(const float4*)(Bp + K0 + 4 * i);
        }

        BF16_CHUNK_COMPUTE(A1, A2, B1, B2);
        __syncthreads();
    }

    BF16_EPILOGUE();
}

// ---------------- init ----------------
__global__ void zero_cnt_kernel() {
    if (threadIdx.x < NG) g_cnt[threadIdx.x] = 0;
}

// ---------------- K2: persistent recurrence ----------------
// 3 independent mma accumulator chains (A1B1 / A2B1 / A1B2), two-phase cp.async
// staging (k-pairs 0-127 then 128-255, second phase hidden behind first compute),
// per-warp release (64 arrivals per group-step).
#define REC_SMEM_BYTES ((2 * 64 * KS32 + 2 * 16 * KS32) * 4)   // 166400

__global__ void __launch_bounds__(256) rnn_rec_kernel(const float* __restrict__ w_hh)
{
    extern __shared__ uint32_t su[];
    uint32_t* W1 = su;                    // [64][260] bf16x2 pairs
    uint32_t* W2 = W1 + 64 * KS32;
    uint32_t* H1 = W2 + 64 * KS32;        // [16][260]
    uint32_t* H2 = H1 + 16 * KS32;

    const int tid = threadIdx.x;
    const int g = blockIdx.x >> 3;
    const int s = blockIdx.x & 7;
    const int n0 = s * NS;
    const int b0 = g * BT;

    // split W slice once
    for (int idx = tid; idx < 64 * 256; idx += 256) {
        const int n = idx >> 8, kp = idx & 255;
        const float f0 = w_hh[(size_t)(n0 + n) * H_ + 2 * kp];
        const float f1 = w_hh[(size_t)(n0 + n) * H_ + 2 * kp + 1];
        split_pair(f0, f1, W1[n * KS32 + kp], W2[n * KS32 + kp]);
    }
    for (int i = tid; i < 2 * 16 * KS32; i += 256) H1[i] = 0u;

    const int wid = tid >> 5, lane = tid & 31;
    const int gid = lane >> 2, tig = lane & 3;

    const uint32_t* h1a = H1 + gid * KS32;
    const uint32_t* h1b = H1 + (gid + 8) * KS32;
    const uint32_t* h2a = H2 + gid * KS32;
    const uint32_t* h2b = H2 + (gid + 8) * KS32;
    const uint32_t* w1p = W1 + (wid * 8 + gid) * KS32;
    const uint32_t* w2p = W2 + (wid * 8 + gid) * KS32;

    const uint32_t H1u = smem_u32(H1);
    const uint32_t H2u = smem_u32(H2);

    const size_t ob1 = ((size_t)(b0 + gid)) * H_ + n0 + wid * 8 + 2 * tig;
    const size_t ob2 = ob1 + (size_t)8 * H_;
    const int    kp1 = (b0 + gid) * 256 + (n0 >> 1) + wid * 4 + tig;
    const int    kp2 = kp1 + 8 * 256;

    const int* cntp = &g_cnt[g];

    __syncthreads();

    for (int t = 0; t < T_; t++) {
        const size_t tb = (size_t)t * B_ * H_;
        const float2 xv1 = __ldcs((const float2*)(g_xp + tb + ob1));
        const float2 xv2 = __ldcs((const float2*)(g_xp + tb + ob2));

        // --- acquire h_{t-1} + two-phase cp.async staging ---
        if (t > 0) {
            unsigned int v;
            do {
                asm volatile("ld.acquire.gpu.global.b32 %0, [%1];" : "=r"(v) : "l"(cntp));
            } while (v < (unsigned int)(NSL * 8 * t));
            const uint32_t* s1 = g_h1f + (size_t)(t - 1) * B_ * 256;
            const uint32_t* s2 = g_h2f + (size_t)(t - 1) * B_ * 256;
            // phase 0: k-pairs 0..127  (q 0..31)
#pragma unroll
            for (int j = 0; j < 2; j++) {
                const int c2 = tid + (j << 8);        // 0..511
                const int row = c2 >> 5, q = c2 & 31;
                const uint32_t dof = (uint32_t)(row * KS32 + q * 4) * 4;
                const size_t   sof = (size_t)(b0 + row) * 256 + q * 4;
                cp_async16(H1u + dof, s1 + sof);
                cp_async16(H2u + dof, s2 + sof);
            }
            CP_COMMIT();
            // phase 1: k-pairs 128..255 (q 32..63)
#pragma unroll
            for (int j = 0; j < 2; j++) {
                const int c2 = tid + (j << 8);
                const int row = c2 >> 5, q = (c2 & 31) + 32;
                const uint32_t dof = (uint32_t)(row * KS32 + q * 4) * 4;
                const size_t   sof = (size_t)(b0 + row) * 256 + q * 4;
                cp_async16(H1u + dof, s1 + sof);
                cp_async16(H2u + dof, s2 + sof);
            }
            CP_COMMIT();
            CP_WAIT(1);    // phase 0 landed; phase 1 still in flight
        }
        __syncthreads();

        // --- compute: 3 independent accumulator chains ---
        float c1[4] = {0, 0, 0, 0}, c2_[4] = {0, 0, 0, 0}, c3[4] = {0, 0, 0, 0};
#pragma unroll 8
        for (int kb = 0; kb < 16; kb++) {
            const int off = kb * 8 + tig;
            uint32_t A1[4], A2[4], B1[2], B2[2];
            A1[0] = h1a[off];     A1[1] = h1b[off];
            A1[2] = h1a[off + 4]; A1[3] = h1b[off + 4];
            A2[0] = h2a[off];     A2[1] = h2b[off];
            A2[2] = h2a[off + 4]; A2[3] = h2b[off + 4];
            B1[0] = w1p[off];     B1[1] = w1p[off + 4];
            B2[0] = w2p[off];     B2[1] = w2p[off + 4];
            mma16n8k16_bf16(c1,  A1, B1);
            mma16n8k16_bf16(c2_, A2, B1);
            mma16n8k16_bf16(c3,  A1, B2);
        }
        if (t > 0) { CP_WAIT(0); }
        __syncthreads();
#pragma unroll 8
        for (int kb = 16; kb < 32; kb++) {
            const int off = kb * 8 + tig;
            uint32_t A1[4], A2[4], B1[2], B2[2];
            A1[0] = h1a[off];     A1[1] = h1b[off];
            A1[2] = h1a[off + 4]; A1[3] = h1b[off + 4];
            A2[0] = h2a[off];     A2[1] = h2b[off];
            A2[2] = h2a[off + 4]; A2[3] = h2b[off + 4];
            B1[0] = w1p[off];     B1[1] = w1p[off + 4];
            B2[0] = w2p[off];     B2[1] = w2p[off + 4];
            mma16n8k16_bf16(c1,  A1, B1);
            mma16n8k16_bf16(c2_, A2, B1);
            mma16n8k16_bf16(c3,  A1, B2);
        }

        // --- epilogue: sum chains, tanh, publish pre-split bf16x2; per-warp release ---
        {
            uint32_t* d1 = g_h1f + tb / 2;
            uint32_t* d2 = g_h2f + tb / 2;
            float2 o1, o2;
            o1.x = tanhf(c1[0] + c2_[0] + c3[0] + xv1.x);
            o1.y = tanhf(c1[1] + c2_[1] + c3[1] + xv1.y);
            o2.x = tanhf(c1[2] + c2_[2] + c3[2] + xv2.x);
            o2.y = tanhf(c1[3] + c2_[3] + c3[3] + xv2.y);
            split_pair(o1.x, o1.y, d1[kp1], d2[kp1]);
            split_pair(o2.x, o2.y, d1[kp2], d2[kp2]);
        }
        __syncwarp();
        if (lane == 0) {
            asm volatile("red.release.gpu.global.add.u32 [%0], %1;"
                         :: "l"(cntp), "r"(1u) : "memory");
        }
        __syncthreads();   // protect H1/H2 before next step's staging
    }
}

// ---------------- launch ----------------
extern "C" void kernel_launch(void* const* d_in, const int* in_sizes, int n_in,
                              void* d_out, int out_size)
{
    const float* x    = (const float*)d_in[0];
    const float* w_ih = (const float*)d_in[1];
    const float* w_hh = (const float*)d_in[2];
    const float* b_ih = (const float*)d_in[3];
    const float* b_hh = (const float*)d_in[4];
    const float* w_fc = (const float*)d_in[5];
    const float* b_fc = (const float*)d_in[6];
    float* out = (float*)d_out;

    float* xp = nullptr;
    uint32_t* h1 = nullptr;
    uint32_t* h2 = nullptr;
    cudaGetSymbolAddress((void**)&xp, g_xp);
    cudaGetSymbolAddress((void**)&h1, g_h1f);
    cudaGetSymbolAddress((void**)&h2, g_h2f);

    cudaFuncSetAttribute(rnn_rec_kernel, cudaFuncAttributeMaxDynamicSharedMemorySize, REC_SMEM_BYTES);
    cudaFuncSetAttribute(bf16_gemm_f32_kernel, cudaFuncAttributeMaxDynamicSharedMemorySize, GEMM_SMEM_BYTES);
    cudaFuncSetAttribute(bf16_gemm_preA_kernel, cudaFuncAttributeMaxDynamicSharedMemorySize, GEMM_SMEM_BYTES);

    const int M = T_ * B_;

    zero_cnt_kernel<<<1, 32>>>();

    // K1: xp = x @ w_ih^T + (b_ih + b_hh)
    bf16_gemm_f32_kernel<<<dim3(H_ / 128, M / 128), 256, GEMM_SMEM_BYTES>>>(
        x, w_ih, b_ih, b_hh, xp, M, H_, I_);

    // K2: recurrence (persistent, 128 CTAs)
    rnn_rec_kernel<<<NG * NSL, 256, REC_SMEM_BYTES>>>(w_hh);

    // K3: out = hs @ w_fc^T + b_fc — A pre-split
    bf16_gemm_preA_kernel<<<dim3(I_ / 128, M / 128), 256, GEMM_SMEM_BYTES>>>(
        h1, h2, w_fc, b_fc, nullptr, out, M, I_, H_);
}